// round 1
// baseline (speedup 1.0000x reference)
#include <cuda_runtime.h>
#include <stdint.h>

#define B_  32
#define C_  256
#define H_  56
#define W_  56
#define HW_ (H_*W_)
#define CO_ 256
#define WORDS 8   // 256 channels / 32 bits

// Scratch (allocation-free rule: __device__ globals)
__device__ uint32_t g_xbits[(size_t)WORDS * B_ * HW_];  // [j][b][hw]
__device__ uint32_t g_wbits[(size_t)CO_ * 9 * WORDS];   // [co][tap][j]
__device__ float    g_coeff[CO_];

// ---------------------------------------------------------------------------
// Kernel A: mix K weight replicas, compute per-co scale, pack sign bits.
// grid = 256 (co), block = 256 (ci)
// ---------------------------------------------------------------------------
__global__ void prep_weights(const float* __restrict__ w,
                             const float* __restrict__ rv,
                             const float* __restrict__ alpha) {
    int co = blockIdx.x;
    int ci = threadIdx.x;
    float r0 = rv[0], r1 = rv[1], r2 = rv[2], r3 = rv[3];
    const size_t kstride = (size_t)CO_ * C_ * 9;
    const float* p = w + ((size_t)co * C_ + ci) * 9;

    float rw[9];
    float asum = 0.f;
#pragma unroll
    for (int t = 0; t < 9; t++) {
        float v = r0 * p[t] + r1 * p[kstride + t] + r2 * p[2 * kstride + t]
                + r3 * p[3 * kstride + t];
        rw[t] = v;
        asum += fabsf(v);
    }

    __shared__ float red[256];
    red[ci] = asum;
    __syncthreads();
    for (int s = 128; s > 0; s >>= 1) {
        if (ci < s) red[ci] += red[ci + s];
        __syncthreads();
    }

    int lane = ci & 31, warp = ci >> 5;
#pragma unroll
    for (int t = 0; t < 9; t++) {
        unsigned bal = __ballot_sync(0xffffffffu, rw[t] < 0.f);
        if (lane == 0) g_wbits[((size_t)co * 9 + t) * WORDS + warp] = bal;
    }
    if (ci == 0) g_coeff[co] = alpha[co] * (red[0] / 2304.0f);
}

// ---------------------------------------------------------------------------
// Kernel B: binarize x into per-pixel channel bitmasks, planar per word.
// bit c of word j == 1  <=>  x[b][j*32+c][hw] < 0
// grid = (ceil(HW/256), 8, 32), block = 256
// ---------------------------------------------------------------------------
__global__ void pack_x(const float* __restrict__ x) {
    int hw = blockIdx.x * blockDim.x + threadIdx.x;
    if (hw >= HW_) return;
    int j = blockIdx.y;
    int b = blockIdx.z;
    const float* p = x + ((size_t)b * C_ + j * 32) * HW_ + hw;
    uint32_t word = 0;
#pragma unroll
    for (int c = 0; c < 32; c++) {
        uint32_t s = __float_as_uint(p[(size_t)c * HW_]) & 0x80000000u;
        word |= s >> (31 - c);   // only bit 31 can be set in s
    }
    g_xbits[((size_t)j * B_ + b) * HW_ + hw] = word;
}

// ---------------------------------------------------------------------------
// Kernel C: XNOR-popcount conv.
// Block: one (b, h) row x 64 output channels. blockDim = (64, 4).
// Thread: pixel w = threadIdx.x (active < 56), 16 consecutive co.
// acc = sum over VALID taps of popc(x ^ w); out = coeff * (256*nvalid - 2*acc)
// ---------------------------------------------------------------------------
__global__ void __launch_bounds__(256) bconv(float* __restrict__ out) {
    __shared__ uint32_t ws[9][WORDS][64];  // [tap][j][c]  (transposed for uint4)
    __shared__ uint32_t xs[3][WORDS][64];  // [row][j][w+kw], cols 1..56 valid
    __shared__ float    cf[64];

    int tid   = threadIdx.y * 64 + threadIdx.x;
    int cogrp = blockIdx.x;   // 0..3  -> co base cogrp*64
    int h     = blockIdx.y;   // 0..55
    int b     = blockIdx.z;   // 0..31

    // weights -> smem (transpose [co][tap*8+j] -> [tap][j][c])
    for (int idx = tid; idx < 64 * 72; idx += 256) {
        int c  = idx / 72;
        int tj = idx - c * 72;
        ws[tj >> 3][tj & 7][c] = g_wbits[(size_t)(cogrp * 64 + c) * 72 + tj];
    }
    if (tid < 64) cf[tid] = g_coeff[cogrp * 64 + tid];

    // x tile rows h-1..h+1 (only in-range rows loaded; OOB rows never read)
    for (int idx = tid; idx < 3 * WORDS * 56; idx += 256) {
        int row = idx / (WORDS * 56);
        int rem = idx - row * (WORDS * 56);
        int j   = rem / 56;
        int col = rem - j * 56;
        int gh  = h - 1 + row;
        if (gh >= 0 && gh < H_)
            xs[row][j][col + 1] =
                g_xbits[((size_t)j * B_ + b) * HW_ + (size_t)gh * W_ + col];
    }
    __syncthreads();

    int  w      = threadIdx.x;
    bool wact   = (w < W_);
    int  cobase = threadIdx.y * 16;

    int acc[16];
#pragma unroll
    for (int i = 0; i < 16; i++) acc[i] = 0;

#pragma unroll
    for (int kh = 0; kh < 3; kh++) {
        int gh = h - 1 + kh;
        if (gh < 0 || gh >= H_) continue;       // uniform over block
#pragma unroll
        for (int kw = 0; kw < 3; kw++) {
            int  gw = w - 1 + kw;
            bool cv = wact && (gw >= 0) && (gw < W_);
            if (cv) {
                int t = kh * 3 + kw;
#pragma unroll
                for (int j = 0; j < WORDS; j++) {
                    uint32_t xw = xs[kh][j][w + kw];
                    const uint4* wp = (const uint4*)&ws[t][j][cobase];
#pragma unroll
                    for (int g = 0; g < 4; g++) {
                        uint4 v = wp[g];
                        acc[g * 4 + 0] += __popc(xw ^ v.x);
                        acc[g * 4 + 1] += __popc(xw ^ v.y);
                        acc[g * 4 + 2] += __popc(xw ^ v.z);
                        acc[g * 4 + 3] += __popc(xw ^ v.w);
                    }
                }
            }
        }
    }

    if (!wact) return;
    int rc   = 3 - (h == 0) - (h == H_ - 1);
    int cc   = 3 - (w == 0) - (w == W_ - 1);
    int base = 256 * rc * cc;

    size_t o = ((size_t)(b * CO_ + cogrp * 64) * H_ + h) * W_ + w;
#pragma unroll
    for (int i = 0; i < 16; i++) {
        int co = cobase + i;
        out[o + (size_t)co * HW_] = cf[co] * (float)(base - 2 * acc[i]);
    }
}

// ---------------------------------------------------------------------------
extern "C" void kernel_launch(void* const* d_in, const int* in_sizes, int n_in,
                              void* d_out, int out_size) {
    const float *x = nullptr, *wt = nullptr, *rv = nullptr, *al = nullptr;
    for (int i = 0; i < n_in; i++) {
        switch (in_sizes[i]) {
            case 25690112: x  = (const float*)d_in[i]; break;  // [32,256,56,56]
            case 2359296:  wt = (const float*)d_in[i]; break;  // [4,256,256,3,3]
            case 5:        rv = (const float*)d_in[i]; break;  // RV
            case 256:      al = (const float*)d_in[i]; break;  // alpha
        }
    }

    prep_weights<<<256, 256>>>(wt, rv, al);

    dim3 gp((HW_ + 255) / 256, WORDS, B_);
    pack_x<<<gp, 256>>>(x);

    dim3 gc(4, H_, B_);
    dim3 bc(64, 4, 1);
    bconv<<<gc, bc>>>((float*)d_out);
}

// round 3
// speedup vs baseline: 1.7154x; 1.7154x over previous
#include <cuda_runtime.h>
#include <stdint.h>

#define B_   32
#define CI_  256
#define H_   56
#define W_   56
#define HW_  3136
#define CO_  256
#define HP_  58
#define WP_  58

// ---------------- scratch (__device__ globals: allocation-free rule) -------
__device__ int8_t g_xpad[(size_t)B_ * HP_ * WP_ * CI_];   // NHWC padded signs (27.5 MB)
__device__ int8_t g_wsign[9 * CO_ * CI_];                 // [tap][co][ci]
__device__ float  g_coeff[CO_];

// ---------------- helpers ---------------------------------------------------
__device__ __forceinline__ void cpa16(void* d, const void* g) {
    uint32_t da;
    asm("{ .reg .u64 t; cvta.to.shared.u64 t, %1; cvt.u32.u64 %0, t; }"
        : "=r"(da) : "l"(d));
    asm volatile("cp.async.cg.shared.global [%0], [%1], 16;" :: "r"(da), "l"(g) : "memory");
}
__device__ __forceinline__ void imma(int* c, uint32_t a0, uint32_t a1, uint32_t a2,
                                     uint32_t a3, uint32_t b0, uint32_t b1) {
    asm volatile(
        "mma.sync.aligned.m16n8k32.row.col.s32.s8.s8.s32 "
        "{%0,%1,%2,%3}, {%4,%5,%6,%7}, {%8,%9}, {%0,%1,%2,%3};"
        : "+r"(c[0]), "+r"(c[1]), "+r"(c[2]), "+r"(c[3])
        : "r"(a0), "r"(a1), "r"(a2), "r"(a3), "r"(b0), "r"(b1));
}
// swizzled smem read: 16B chunk index XOR (row & 7); rows are 128B
__device__ __forceinline__ uint32_t lds_sw(const char* base, int row, int col) {
    int ch = (col >> 4) ^ (row & 7);
    return *(const uint32_t*)(base + row * 128 + (ch << 4) + (col & 15));
}

// ---------------- kernel A: weights -> int8 signs + coeff -------------------
__global__ void prep_weights(const float* __restrict__ w,
                             const float* __restrict__ rv,
                             const float* __restrict__ alpha) {
    int co = blockIdx.x, ci = threadIdx.x;
    float r0 = rv[0], r1 = rv[1], r2 = rv[2], r3 = rv[3];
    const size_t ks = (size_t)CO_ * CI_ * 9;
    const float* p = w + ((size_t)co * CI_ + ci) * 9;
    float asum = 0.f;
#pragma unroll
    for (int t = 0; t < 9; t++) {
        float v = r0 * p[t] + r1 * p[ks + t] + r2 * p[2 * ks + t] + r3 * p[3 * ks + t];
        asum += fabsf(v);
        g_wsign[((size_t)t * CO_ + co) * CI_ + ci] = v > 0.f ? 1 : (v < 0.f ? -1 : 0);
    }
    __shared__ float red[256];
    red[ci] = asum;
    __syncthreads();
    for (int s = 128; s > 0; s >>= 1) {
        if (ci < s) red[ci] += red[ci + s];
        __syncthreads();
    }
    if (ci == 0) g_coeff[co] = alpha[co] * (red[0] / 2304.0f);
}

// ---------------- kernel B0: zero the pad ring ------------------------------
__global__ void zero_pad() {
    int b = blockIdx.y, i = blockIdx.x, t = threadIdx.x;
    int r, c;
    if (i < 58)       { r = 0;  c = i; }
    else if (i < 116) { r = 57; c = i - 58; }
    else { int j = i - 116; r = 1 + (j >> 1); c = (j & 1) * 57; }
    uint2* dst = (uint2*)&g_xpad[(((size_t)b * HP_ + r) * WP_ + c) * CI_];
    dst[t] = make_uint2(0, 0);
}

// ---------------- kernel B1: NCHW f32 -> NHWC-padded int8 signs -------------
__global__ void pack_x(const float* __restrict__ x) {
    __shared__ uint32_t tile[32][65];   // [px][ci/4], padded stride
    int b = blockIdx.y;
    int hw0 = blockIdx.x * 32;
    int tid = threadIdx.x;
    int tx = tid & 31, ty = tid >> 5;   // ty 0..7
    const float* xp = x + (size_t)b * CI_ * HW_ + hw0 + tx;
#pragma unroll
    for (int k4 = 0; k4 < 8; k4++) {
        uint32_t pk = 0;
#pragma unroll
        for (int j = 0; j < 4; j++) {
            int ci = ty * 32 + k4 * 4 + j;
            float v = xp[(size_t)ci * HW_];
            int8_t s = v > 0.f ? 1 : (v < 0.f ? -1 : 0);
            pk |= ((uint32_t)(uint8_t)s) << (8 * j);
        }
        tile[tx][ty * 8 + k4] = pk;
    }
    __syncthreads();
    int p = tid >> 3, c8 = tid & 7;
    int hw = hw0 + p;
    int r = hw / 56, c = hw - r * 56;
    uint4* d = (uint4*)&g_xpad[(((size_t)b * HP_ + r + 1) * WP_ + c + 1) * CI_ + c8 * 32];
    d[0] = make_uint4(tile[p][c8 * 8 + 0], tile[p][c8 * 8 + 1],
                      tile[p][c8 * 8 + 2], tile[p][c8 * 8 + 3]);
    d[1] = make_uint4(tile[p][c8 * 8 + 4], tile[p][c8 * 8 + 5],
                      tile[p][c8 * 8 + 6], tile[p][c8 * 8 + 7]);
}

// ---------------- kernel C: int8 IMMA implicit-GEMM conv --------------------
// CTA: M=128 px (2 rows x 56, +16 pad) x N=128 co. K: 18 chunks of 128.
// 8 warps: warp tile 64x32. 3-stage cp.async pipeline, 32KB/stage.
#define STG 32768
#define CF_OFF (3 * STG)
#define SMEM_DYN (CF_OFF + 512)

__device__ __forceinline__ void load_stage(char* stg, int i, int r0, int b,
                                           int coBase, int tid) {
    int tap = i >> 1, ciofs = (i & 1) << 7;
    int kh = tap / 3, kw = tap - kh * 3;
#pragma unroll
    for (int t = 0; t < 4; t++) {   // A: 128 rows x 128B
        int idx = tid + t * 256;
        int row = idx >> 3, e = idx & 7;
        int px = row - (row >= 112 ? 112 : 0);
        int j = px >= 56;
        int w = px - (j ? 56 : 0);
        const void* g = &g_xpad[(((size_t)b * HP_ + r0 + j + kh) * WP_ + w + kw) * CI_
                                + ciofs + e * 16];
        cpa16(stg + row * 128 + ((e ^ (row & 7)) << 4), g);
    }
#pragma unroll
    for (int t = 0; t < 4; t++) {   // B: 128 co x 128B
        int idx = tid + t * 256;
        int row = idx >> 3, e = idx & 7;
        const void* g = &g_wsign[((size_t)tap * CO_ + coBase + row) * CI_ + ciofs + e * 16];
        cpa16(stg + 16384 + row * 128 + ((e ^ (row & 7)) << 4), g);
    }
}

__global__ void __launch_bounds__(256) bconv_imma(float* __restrict__ out) {
    extern __shared__ char smem[];
    int tid = threadIdx.x, wid = tid >> 5, lane = tid & 31;
    int g = lane >> 2, tg = lane & 3;
    int wm = wid >> 2, wn = wid & 3;          // warp tile: (wm*64, wn*32)
    int r0 = blockIdx.x * 2, coBase = blockIdx.y * 128, b = blockIdx.z;

    float* cf = (float*)(smem + CF_OFF);
    if (tid < 128) cf[tid] = g_coeff[coBase + tid];

    int acc[4][4][4];
#pragma unroll
    for (int mf = 0; mf < 4; mf++)
#pragma unroll
        for (int nf = 0; nf < 4; nf++)
#pragma unroll
            for (int e = 0; e < 4; e++) acc[mf][nf][e] = 0;

    load_stage(smem, 0, r0, b, coBase, tid);
    asm volatile("cp.async.commit_group;" ::: "memory");
    load_stage(smem + STG, 1, r0, b, coBase, tid);
    asm volatile("cp.async.commit_group;" ::: "memory");

    for (int i = 0; i < 18; i++) {
        if (i >= 1) __syncthreads();          // slot (i+2)%3 free to overwrite
        if (i + 2 < 18) {
            load_stage(smem + ((i + 2) % 3) * STG, i + 2, r0, b, coBase, tid);
            asm volatile("cp.async.commit_group;" ::: "memory");
            asm volatile("cp.async.wait_group 2;" ::: "memory");
        } else if (i + 1 < 18) {
            asm volatile("cp.async.wait_group 1;" ::: "memory");
        } else {
            asm volatile("cp.async.wait_group 0;" ::: "memory");
        }
        __syncthreads();

        const char* As = smem + (i % 3) * STG;
        const char* Bs = As + 16384;
#pragma unroll
        for (int k = 0; k < 4; k++) {
            int cb = k * 32;
            uint32_t a[4][4];
#pragma unroll
            for (int mf = 0; mf < 4; mf++) {
                int r = wm * 64 + mf * 16 + g;
                a[mf][0] = lds_sw(As, r,     cb + tg * 4);
                a[mf][1] = lds_sw(As, r + 8, cb + tg * 4);
                a[mf][2] = lds_sw(As, r,     cb + 16 + tg * 4);
                a[mf][3] = lds_sw(As, r + 8, cb + 16 + tg * 4);
            }
#pragma unroll
            for (int nf = 0; nf < 4; nf++) {
                int rB = wn * 32 + nf * 8 + g;
                uint32_t b0 = lds_sw(Bs, rB, cb + tg * 4);
                uint32_t b1 = lds_sw(Bs, rB, cb + 16 + tg * 4);
#pragma unroll
                for (int mf = 0; mf < 4; mf++)
                    imma(acc[mf][nf], a[mf][0], a[mf][1], a[mf][2], a[mf][3], b0, b1);
            }
        }
    }

    // epilogue: out[b][co][h][w] = coeff[co] * acc   (NCHW)
    float* obase = out + (size_t)b * CO_ * HW_;
#pragma unroll
    for (int mf = 0; mf < 4; mf++) {
#pragma unroll
        for (int half = 0; half < 2; half++) {
            int px = wm * 64 + mf * 16 + g + 8 * half;
            if (px < 112) {
                int j = px >= 56;
                int h = r0 + j;
                int w = px - (j ? 56 : 0);
#pragma unroll
                for (int nf = 0; nf < 4; nf++) {
                    int cl = wn * 32 + nf * 8 + tg * 2;
                    int co = coBase + cl;
                    float* o = obase + (size_t)co * HW_ + h * 56 + w;
                    o[0]   = cf[cl]     * (float)acc[mf][nf][half * 2];
                    o[HW_] = cf[cl + 1] * (float)acc[mf][nf][half * 2 + 1];
                }
            }
        }
    }
}

// ---------------------------------------------------------------------------
extern "C" void kernel_launch(void* const* d_in, const int* in_sizes, int n_in,
                              void* d_out, int out_size) {
    const float *x = nullptr, *wt = nullptr, *rv = nullptr, *al = nullptr;
    for (int i = 0; i < n_in; i++) {
        switch (in_sizes[i]) {
            case 25690112: x  = (const float*)d_in[i]; break;
            case 2359296:  wt = (const float*)d_in[i]; break;
            case 5:        rv = (const float*)d_in[i]; break;
            case 256:      al = (const float*)d_in[i]; break;
        }
    }

    prep_weights<<<256, 256>>>(wt, rv, al);

    dim3 gz(228, 32);
    zero_pad<<<gz, 32>>>();

    dim3 gp(98, 32);
    pack_x<<<gp, 256>>>(x);

    static int smem_set = 0;
    if (!smem_set) {
        cudaFuncSetAttribute(bconv_imma, cudaFuncAttributeMaxDynamicSharedMemorySize,
                             SMEM_DYN);
        smem_set = 1;
    }
    dim3 gc(28, 2, 32);
    bconv_imma<<<gc, 256, SMEM_DYN>>>((float*)d_out);
}

// round 4
// speedup vs baseline: 1.7829x; 1.0393x over previous
#include <cuda_runtime.h>
#include <stdint.h>

#define B_   32
#define CI_  256
#define H_   56
#define W_   56
#define HW_  3136
#define CO_  256
#define HP_  58
#define WP_  58

// ---------------- scratch (__device__ globals: allocation-free rule) -------
__device__ int8_t g_xpad[(size_t)B_ * HP_ * WP_ * CI_];   // NHWC padded signs (27.5 MB)
__device__ int8_t g_wsign[9 * CO_ * CI_];                 // [tap][co][ci]
__device__ float  g_coeff[CO_];

// ---------------- helpers ---------------------------------------------------
__device__ __forceinline__ uint32_t s2u(const void* p) {
    uint32_t a;
    asm("{ .reg .u64 t; cvta.to.shared.u64 t, %1; cvt.u32.u64 %0, t; }"
        : "=r"(a) : "l"(p));
    return a;
}
__device__ __forceinline__ void cpa16(void* d, const void* g) {
    uint32_t da;
    asm("{ .reg .u64 t; cvta.to.shared.u64 t, %1; cvt.u32.u64 %0, t; }"
        : "=r"(da) : "l"(d));
    asm volatile("cp.async.cg.shared.global [%0], [%1], 16;" :: "r"(da), "l"(g) : "memory");
}
__device__ __forceinline__ void imma(int* c, const uint32_t* a, uint32_t b0, uint32_t b1) {
    asm volatile(
        "mma.sync.aligned.m16n8k32.row.col.s32.s8.s8.s32 "
        "{%0,%1,%2,%3}, {%4,%5,%6,%7}, {%8,%9}, {%0,%1,%2,%3};"
        : "+r"(c[0]), "+r"(c[1]), "+r"(c[2]), "+r"(c[3])
        : "r"(a[0]), "r"(a[1]), "r"(a[2]), "r"(a[3]), "r"(b0), "r"(b1));
}
__device__ __forceinline__ void ldm4(uint32_t* r, uint32_t addr) {
    asm volatile("ldmatrix.sync.aligned.m8n8.x4.shared.b16 {%0,%1,%2,%3}, [%4];"
                 : "=r"(r[0]), "=r"(r[1]), "=r"(r[2]), "=r"(r[3]) : "r"(addr));
}

// ---------------- kernel A: weights -> int8 signs + coeff -------------------
__global__ void prep_weights(const float* __restrict__ w,
                             const float* __restrict__ rv,
                             const float* __restrict__ alpha) {
    int co = blockIdx.x, ci = threadIdx.x;
    float r0 = rv[0], r1 = rv[1], r2 = rv[2], r3 = rv[3];
    const size_t ks = (size_t)CO_ * CI_ * 9;
    const float* p = w + ((size_t)co * CI_ + ci) * 9;
    float asum = 0.f;
#pragma unroll
    for (int t = 0; t < 9; t++) {
        float v = r0 * p[t] + r1 * p[ks + t] + r2 * p[2 * ks + t] + r3 * p[3 * ks + t];
        asum += fabsf(v);
        g_wsign[((size_t)t * CO_ + co) * CI_ + ci] = v > 0.f ? 1 : (v < 0.f ? -1 : 0);
    }
    __shared__ float red[256];
    red[ci] = asum;
    __syncthreads();
    for (int s = 128; s > 0; s >>= 1) {
        if (ci < s) red[ci] += red[ci + s];
        __syncthreads();
    }
    if (ci == 0) g_coeff[co] = alpha[co] * (red[0] / 2304.0f);
}

// ---------------- kernel B0: zero the pad ring ------------------------------
__global__ void zero_pad() {
    int b = blockIdx.y, i = blockIdx.x, t = threadIdx.x;
    int r, c;
    if (i < 58)       { r = 0;  c = i; }
    else if (i < 116) { r = 57; c = i - 58; }
    else { int j = i - 116; r = 1 + (j >> 1); c = (j & 1) * 57; }
    uint2* dst = (uint2*)&g_xpad[(((size_t)b * HP_ + r) * WP_ + c) * CI_];
    dst[t] = make_uint2(0, 0);
}

// ---------------- kernel B1: NCHW f32 -> NHWC-padded int8 signs -------------
__global__ void pack_x(const float* __restrict__ x) {
    __shared__ uint32_t tile[32][65];
    int b = blockIdx.y;
    int hw0 = blockIdx.x * 32;
    int tid = threadIdx.x;
    int tx = tid & 31, ty = tid >> 5;
    const float* xp = x + (size_t)b * CI_ * HW_ + hw0 + tx;
#pragma unroll
    for (int k4 = 0; k4 < 8; k4++) {
        uint32_t pk = 0;
#pragma unroll
        for (int j = 0; j < 4; j++) {
            int ci = ty * 32 + k4 * 4 + j;
            float v = xp[(size_t)ci * HW_];
            int8_t s = v > 0.f ? 1 : (v < 0.f ? -1 : 0);
            pk |= ((uint32_t)(uint8_t)s) << (8 * j);
        }
        tile[tx][ty * 8 + k4] = pk;
    }
    __syncthreads();
    int p = tid >> 3, c8 = tid & 7;
    int hw = hw0 + p;
    int r = hw / 56, c = hw - r * 56;
    uint4* d = (uint4*)&g_xpad[(((size_t)b * HP_ + r + 1) * WP_ + c + 1) * CI_ + c8 * 32];
    d[0] = make_uint4(tile[p][c8 * 8 + 0], tile[p][c8 * 8 + 1],
                      tile[p][c8 * 8 + 2], tile[p][c8 * 8 + 3]);
    d[1] = make_uint4(tile[p][c8 * 8 + 4], tile[p][c8 * 8 + 5],
                      tile[p][c8 * 8 + 6], tile[p][c8 * 8 + 7]);
}

// ---------------- kernel C: int8 IMMA implicit-GEMM conv --------------------
// CTA: 512 thr (16 warps, 4x4 warp grid, warp tile 32x32).
// M=128 px (2 rows x 56 + 16 dup) x N=128 co. K: 18 chunks of 128 ci-bytes.
// 4-stage cp.async pipeline (32KB/stage), one __syncthreads per chunk.
#define STG 32768
#define NSTG 4
#define CF_OFF (NSTG * STG)
#define SMEM_DYN (CF_OFF + 512)

__device__ __forceinline__ void load_stage(char* smem, int slot, int i, int r0,
                                           int b, int coBase, int tid) {
    int tap = i >> 1, ciofs = (i & 1) << 7;
    int kh = tap / 3, kw = tap - kh * 3;
    char* stg = smem + slot * STG;
#pragma unroll
    for (int t = 0; t < 2; t++) {       // A: 128 rows x 128B
        int idx = tid + t * 512;
        int row = idx >> 3, e = idx & 7;
        int px = row >= 112 ? row - 112 : row;
        int j = px >= 56;
        int w = px - (j ? 56 : 0);
        const void* g = &g_xpad[(((size_t)b * HP_ + r0 + j + kh) * WP_ + w + kw) * CI_
                                + ciofs + e * 16];
        cpa16(stg + row * 128 + ((e ^ (row & 7)) << 4), g);
    }
#pragma unroll
    for (int t = 0; t < 2; t++) {       // B: 128 co x 128B
        int idx = tid + t * 512;
        int row = idx >> 3, e = idx & 7;
        const void* g = &g_wsign[((size_t)tap * CO_ + coBase + row) * CI_ + ciofs + e * 16];
        cpa16(stg + 16384 + row * 128 + ((e ^ (row & 7)) << 4), g);
    }
}

#define LDFRAG(buf, s)                                                          \
    {                                                                           \
        int c16 = ((s) << 1) + khalf;                                           \
        ldm4(a[buf][0],  aS + rowA0 * 128 + (((c16) ^ (rowA0 & 7)) << 4));      \
        ldm4(a[buf][1],  aS + rowA1 * 128 + (((c16) ^ (rowA1 & 7)) << 4));      \
        ldm4(bb[buf][0], bS + rowB0 * 128 + (((c16) ^ (rowB0 & 7)) << 4));      \
        ldm4(bb[buf][1], bS + rowB1 * 128 + (((c16) ^ (rowB1 & 7)) << 4));      \
    }

__global__ void __launch_bounds__(512, 1) bconv_imma(float* __restrict__ out) {
    extern __shared__ char smem[];
    uint32_t sb = s2u(smem);
    int tid = threadIdx.x, wid = tid >> 5, lane = tid & 31;
    int g = lane >> 2, tg = lane & 3;
    int wm = wid >> 2, wn = wid & 3;
    int r0 = blockIdx.x * 2, coBase = blockIdx.y * 128, b = blockIdx.z;

    float* cf = (float*)(smem + CF_OFF);
    if (tid < 128) cf[tid] = g_coeff[coBase + tid];

    // ldmatrix per-lane rows: lane -> (tile t8, row-in-tile lr)
    int t8 = lane >> 3, lr = lane & 7;
    int khalf = t8 >> 1, rsel = (t8 & 1) * 8;
    int rowA0 = wm * 32 + rsel + lr;
    int rowA1 = rowA0 + 16;
    int rowB0 = wn * 32 + rsel + lr;
    int rowB1 = rowB0 + 16;

    int acc[2][4][4];
#pragma unroll
    for (int mf = 0; mf < 2; mf++)
#pragma unroll
        for (int nf = 0; nf < 4; nf++)
#pragma unroll
            for (int e = 0; e < 4; e++) acc[mf][nf][e] = 0;

    // prologue: chunks 0..2 into slots 0..2
#pragma unroll
    for (int s = 0; s < 3; s++) {
        load_stage(smem, s, s, r0, b, coBase, tid);
        asm volatile("cp.async.commit_group;" ::: "memory");
    }
    asm volatile("cp.async.wait_group 2;" ::: "memory");
    __syncthreads();

    for (int i = 0; i < 18; i++) {
        // issue next stage (writes slot (i-1)&3, freed by last iter's barrier)
        if (i + 3 < 18)
            load_stage(smem, (i + 3) & 3, i + 3, r0, b, coBase, tid);
        asm volatile("cp.async.commit_group;" ::: "memory");

        uint32_t aS = sb + (i & 3) * STG;
        uint32_t bS = aS + 16384;
        uint32_t a[2][2][4], bb[2][2][4];
        LDFRAG(0, 0);
#pragma unroll
        for (int s = 0; s < 4; s++) {
            int buf = s & 1;
            if (s < 3) LDFRAG(buf ^ 1, s + 1);
#pragma unroll
            for (int mf = 0; mf < 2; mf++)
#pragma unroll
                for (int p = 0; p < 2; p++) {
                    imma(acc[mf][2 * p],     a[buf][mf], bb[buf][p][0], bb[buf][p][2]);
                    imma(acc[mf][2 * p + 1], a[buf][mf], bb[buf][p][1], bb[buf][p][3]);
                }
        }

        // chunk i+1 complete & visible to all after this wait+barrier
        asm volatile("cp.async.wait_group 2;" ::: "memory");
        __syncthreads();
    }

    // epilogue: out[b][co][h][w] = coeff[co] * acc   (NCHW)
    float* obase = out + (size_t)b * CO_ * HW_;
#pragma unroll
    for (int mf = 0; mf < 2; mf++) {
#pragma unroll
        for (int half = 0; half < 2; half++) {
            int px = wm * 32 + mf * 16 + g + 8 * half;
            if (px < 112) {
                int j = px >= 56;
                int h = r0 + j;
                int w = px - (j ? 56 : 0);
#pragma unroll
                for (int nf = 0; nf < 4; nf++) {
                    int cl = wn * 32 + nf * 8 + tg * 2;
                    float* o = obase + (size_t)(coBase + cl) * HW_ + h * 56 + w;
                    o[0]   = cf[cl]     * (float)acc[mf][nf][half * 2];
                    o[HW_] = cf[cl + 1] * (float)acc[mf][nf][half * 2 + 1];
                }
            }
        }
    }
}

// ---------------------------------------------------------------------------
extern "C" void kernel_launch(void* const* d_in, const int* in_sizes, int n_in,
                              void* d_out, int out_size) {
    const float *x = nullptr, *wt = nullptr, *rv = nullptr, *al = nullptr;
    for (int i = 0; i < n_in; i++) {
        switch (in_sizes[i]) {
            case 25690112: x  = (const float*)d_in[i]; break;
            case 2359296:  wt = (const float*)d_in[i]; break;
            case 5:        rv = (const float*)d_in[i]; break;
            case 256:      al = (const float*)d_in[i]; break;
        }
    }

    prep_weights<<<256, 256>>>(wt, rv, al);

    dim3 gz(228, 32);
    zero_pad<<<gz, 32>>>();

    dim3 gp(98, 32);
    pack_x<<<gp, 256>>>(x);

    static int smem_set = 0;
    if (!smem_set) {
        cudaFuncSetAttribute(bconv_imma, cudaFuncAttributeMaxDynamicSharedMemorySize,
                             SMEM_DYN);
        smem_set = 1;
    }
    dim3 gc(28, 2, 32);
    bconv_imma<<<gc, 512, SMEM_DYN>>>((float*)d_out);
}

// round 5
// speedup vs baseline: 1.8800x; 1.0544x over previous
#include <cuda_runtime.h>
#include <stdint.h>

#define B_   32
#define CI_  256
#define H_   56
#define W_   56
#define HW_  3136
#define CO_  256
#define HP_  58
#define WP_  58

// ---------------- scratch (__device__ globals: allocation-free rule) -------
__device__ int8_t g_xpad[(size_t)B_ * HP_ * WP_ * CI_];   // NHWC padded signs
__device__ int8_t g_wsign[9 * CO_ * CI_];                 // [tap][co][ci]
__device__ float  g_coeff[CO_];

// ---------------- helpers ---------------------------------------------------
__device__ __forceinline__ uint32_t s2u(const void* p) {
    uint32_t a;
    asm("{ .reg .u64 t; cvta.to.shared.u64 t, %1; cvt.u32.u64 %0, t; }"
        : "=r"(a) : "l"(p));
    return a;
}
__device__ __forceinline__ void cpa16(uint32_t d, const void* g) {
    asm volatile("cp.async.cg.shared.global [%0], [%1], 16;" :: "r"(d), "l"(g) : "memory");
}
__device__ __forceinline__ void imma(int* c, const uint32_t* a, uint32_t b0, uint32_t b1) {
    asm volatile(
        "mma.sync.aligned.m16n8k32.row.col.s32.s8.s8.s32 "
        "{%0,%1,%2,%3}, {%4,%5,%6,%7}, {%8,%9}, {%0,%1,%2,%3};"
        : "+r"(c[0]), "+r"(c[1]), "+r"(c[2]), "+r"(c[3])
        : "r"(a[0]), "r"(a[1]), "r"(a[2]), "r"(a[3]), "r"(b0), "r"(b1));
}
__device__ __forceinline__ void ldm4(uint32_t* r, uint32_t addr) {
    asm volatile("ldmatrix.sync.aligned.m8n8.x4.shared.b16 {%0,%1,%2,%3}, [%4];"
                 : "=r"(r[0]), "=r"(r[1]), "=r"(r[2]), "=r"(r[3]) : "r"(addr));
}

// ---------------- kernel A: weights -> int8 signs + coeff -------------------
__global__ void prep_weights(const float* __restrict__ w,
                             const float* __restrict__ rv,
                             const float* __restrict__ alpha) {
    int co = blockIdx.x, ci = threadIdx.x;
    float r0 = rv[0], r1 = rv[1], r2 = rv[2], r3 = rv[3];
    const size_t ks = (size_t)CO_ * CI_ * 9;
    const float* p = w + ((size_t)co * CI_ + ci) * 9;
    float asum = 0.f;
#pragma unroll
    for (int t = 0; t < 9; t++) {
        float v = r0 * p[t] + r1 * p[ks + t] + r2 * p[2 * ks + t] + r3 * p[3 * ks + t];
        asum += fabsf(v);
        g_wsign[((size_t)t * CO_ + co) * CI_ + ci] = v > 0.f ? 1 : (v < 0.f ? -1 : 0);
    }
    __shared__ float red[256];
    red[ci] = asum;
    __syncthreads();
    for (int s = 128; s > 0; s >>= 1) {
        if (ci < s) red[ci] += red[ci + s];
        __syncthreads();
    }
    if (ci == 0) g_coeff[co] = alpha[co] * (red[0] / 2304.0f);
}

// ---------------- kernel B0: zero the pad ring ------------------------------
__global__ void zero_pad() {
    int b = blockIdx.y, i = blockIdx.x, t = threadIdx.x;
    int r, c;
    if (i < 58)       { r = 0;  c = i; }
    else if (i < 116) { r = 57; c = i - 58; }
    else { int j = i - 116; r = 1 + (j >> 1); c = (j & 1) * 57; }
    uint2* dst = (uint2*)&g_xpad[(((size_t)b * HP_ + r) * WP_ + c) * CI_];
    dst[t] = make_uint2(0, 0);
}

// ---------------- kernel B1: NCHW f32 -> NHWC-padded int8 signs -------------
__global__ void pack_x(const float* __restrict__ x) {
    __shared__ uint32_t tile[32][65];
    int b = blockIdx.y;
    int hw0 = blockIdx.x * 32;
    int tid = threadIdx.x;
    int tx = tid & 31, ty = tid >> 5;
    const float* xp = x + (size_t)b * CI_ * HW_ + hw0 + tx;
#pragma unroll
    for (int k4 = 0; k4 < 8; k4++) {
        uint32_t pk = 0;
#pragma unroll
        for (int j = 0; j < 4; j++) {
            int ci = ty * 32 + k4 * 4 + j;
            float v = xp[(size_t)ci * HW_];
            int8_t s = v > 0.f ? 1 : (v < 0.f ? -1 : 0);
            pk |= ((uint32_t)(uint8_t)s) << (8 * j);
        }
        tile[tx][ty * 8 + k4] = pk;
    }
    __syncthreads();
    int p = tid >> 3, c8 = tid & 7;
    int hw = hw0 + p;
    int r = hw / 56, c = hw - r * 56;
    uint4* d = (uint4*)&g_xpad[(((size_t)b * HP_ + r + 1) * WP_ + c + 1) * CI_ + c8 * 32];
    d[0] = make_uint4(tile[p][c8 * 8 + 0], tile[p][c8 * 8 + 1],
                      tile[p][c8 * 8 + 2], tile[p][c8 * 8 + 3]);
    d[1] = make_uint4(tile[p][c8 * 8 + 4], tile[p][c8 * 8 + 5],
                      tile[p][c8 * 8 + 6], tile[p][c8 * 8 + 7]);
}

// ---------------- kernel C: A-resident int8 IMMA implicit-GEMM conv ---------
// CTA: 512 thr, 16 warps (4x4), warp tile 64x32.
// M=256 (4 output rows x 56 px + 32 dup) x N=128 co.
// A: 6 input rows x 58 x 256 resident in smem (loaded once, contiguous gmem).
// B: 18 chunks of [128 co x 128 ci], 4-stage cp.async pipeline (16KB/stage).
#define A_SZ   89088              // 6*58*256
#define STG    16384
#define NSTG   4
#define CF_OFF (A_SZ + NSTG * STG)
#define SMEM_DYN (CF_OFF + 512)

__device__ __forceinline__ void load_B(char* smem, int slot, int i, int coBase, int tid) {
    int tap = i >> 1, ciofs = (i & 1) << 7;
    uint32_t stg = s2u(smem + A_SZ + slot * STG);
    int row = tid >> 3, e = tid & 7;          // 2 rows per thread via stride
#pragma unroll
    for (int t = 0; t < 2; t++) {
        int r = row + t * 64;
        const void* g = &g_wsign[((size_t)tap * CO_ + coBase + r) * CI_ + ciofs + e * 16];
        cpa16(stg + r * 128 + ((e ^ (r & 7)) << 4), g);
    }
}

__global__ void __launch_bounds__(512, 1) bconv_imma(float* __restrict__ out) {
    extern __shared__ char smem[];
    uint32_t sbA = s2u(smem);
    int tid = threadIdx.x, wid = tid >> 5, lane = tid & 31;
    int g = lane >> 2, tg = lane & 3;
    int wm = wid >> 2, wn = wid & 3;
    int r0 = blockIdx.x * 4, coBase = blockIdx.y * 128, b = blockIdx.z;

    float* cf = (float*)(smem + CF_OFF);
    if (tid < 128) cf[tid] = g_coeff[coBase + tid];

    // ---- prologue: A resident (contiguous 89KB) + first 3 B stages ----
    {
        const int8_t* gA = &g_xpad[(((size_t)b * HP_ + r0) * WP_) * CI_];
        for (int idx = tid; idx < A_SZ / 16; idx += 512) {
            int lin = idx >> 4, ch = idx & 15;
            cpa16(sbA + lin * 256 + ((ch ^ (lin & 7)) << 4), gA + idx * 16);
        }
        asm volatile("cp.async.commit_group;" ::: "memory");
#pragma unroll
        for (int s = 0; s < 3; s++) {
            load_B(smem, s, s, coBase, tid);
            asm volatile("cp.async.commit_group;" ::: "memory");
        }
    }

    // per-lane fragment geometry
    int t8 = lane >> 3, lr = lane & 7;
    int khalf = t8 >> 1, rsel = (t8 & 1) * 8;
    int lin0[4];
#pragma unroll
    for (int mf = 0; mf < 4; mf++) {
        int m = wm * 64 + mf * 16 + rsel + lr;
        if (m < 224) { int j = m / 56; lin0[mf] = j * 58 + (m - j * 56); }
        else lin0[mf] = 0;
    }
    int rowB0 = wn * 32 + rsel + lr;
    int rowB1 = rowB0 + 16;
    uint32_t bB0 = rowB0 * 128 + A_SZ, bB1 = rowB1 * 128 + A_SZ;
    int xB0 = rowB0 & 7, xB1 = rowB1 & 7;

    int acc[4][4][4];
#pragma unroll
    for (int mf = 0; mf < 4; mf++)
#pragma unroll
        for (int nf = 0; nf < 4; nf++)
#pragma unroll
            for (int e = 0; e < 4; e++) acc[mf][nf][e] = 0;

    asm volatile("cp.async.wait_group 2;" ::: "memory");   // A + B0 done
    __syncthreads();

    for (int i = 0; i < 18; i++) {
        if (i + 3 < 18) load_B(smem, (i + 3) & 3, i + 3, coBase, tid);
        asm volatile("cp.async.commit_group;" ::: "memory");

        int tap = i >> 1, cihalf = i & 1;
        int kh = tap / 3, kw = tap - kh * 3;
        int dlin = kh * 58 + kw;
        uint32_t aBase[4]; int x7[4];
#pragma unroll
        for (int mf = 0; mf < 4; mf++) {
            int lin = lin0[mf] + dlin;
            aBase[mf] = sbA + lin * 256;
            x7[mf] = lin & 7;
        }
        uint32_t bS = sbA + ((i & 3) * STG);

#pragma unroll
        for (int s = 0; s < 4; s++) {
            int c16a = cihalf * 8 + s * 2 + khalf;
            int c16b = s * 2 + khalf;
            uint32_t a[4][4], bb[2][4];
#pragma unroll
            for (int mf = 0; mf < 4; mf++)
                ldm4(a[mf], aBase[mf] + ((c16a ^ x7[mf]) << 4));
            ldm4(bb[0], bS + bB0 + ((c16b ^ xB0) << 4));
            ldm4(bb[1], bS + bB1 + ((c16b ^ xB1) << 4));
#pragma unroll
            for (int mf = 0; mf < 4; mf++)
#pragma unroll
                for (int p = 0; p < 2; p++) {
                    imma(acc[mf][2 * p],     a[mf], bb[p][0], bb[p][2]);
                    imma(acc[mf][2 * p + 1], a[mf], bb[p][1], bb[p][3]);
                }
        }

        asm volatile("cp.async.wait_group 2;" ::: "memory");  // next B chunk landed
        __syncthreads();
    }

    // ---- epilogue: out[b][co][h][w] = coeff[co] * acc (NCHW) ----
    float* obase = out + (size_t)b * CO_ * HW_;
#pragma unroll
    for (int mf = 0; mf < 4; mf++) {
#pragma unroll
        for (int half = 0; half < 2; half++) {
            int px = wm * 64 + mf * 16 + g + 8 * half;
            if (px < 224) {
                int j = px / 56;
                int h = r0 + j;
                int w = px - j * 56;
#pragma unroll
                for (int nf = 0; nf < 4; nf++) {
                    int cl = wn * 32 + nf * 8 + tg * 2;
                    float* o = obase + (size_t)(coBase + cl) * HW_ + h * 56 + w;
                    o[0]   = cf[cl]     * (float)acc[mf][nf][half * 2];
                    o[HW_] = cf[cl + 1] * (float)acc[mf][nf][half * 2 + 1];
                }
            }
        }
    }
}

// ---------------------------------------------------------------------------
extern "C" void kernel_launch(void* const* d_in, const int* in_sizes, int n_in,
                              void* d_out, int out_size) {
    const float *x = nullptr, *wt = nullptr, *rv = nullptr, *al = nullptr;
    for (int i = 0; i < n_in; i++) {
        switch (in_sizes[i]) {
            case 25690112: x  = (const float*)d_in[i]; break;
            case 2359296:  wt = (const float*)d_in[i]; break;
            case 5:        rv = (const float*)d_in[i]; break;
            case 256:      al = (const float*)d_in[i]; break;
        }
    }

    prep_weights<<<256, 256>>>(wt, rv, al);

    dim3 gz(228, 32);
    zero_pad<<<gz, 32>>>();

    dim3 gp(98, 32);
    pack_x<<<gp, 256>>>(x);

    static int smem_set = 0;
    if (!smem_set) {
        cudaFuncSetAttribute(bconv_imma, cudaFuncAttributeMaxDynamicSharedMemorySize,
                             SMEM_DYN);
        smem_set = 1;
    }
    dim3 gc(14, 2, 32);
    bconv_imma<<<gc, 512, SMEM_DYN>>>((float*)d_out);
}

// round 6
// speedup vs baseline: 2.1151x; 1.1251x over previous
#include <cuda_runtime.h>
#include <stdint.h>

#define B_   32
#define CI_  256
#define H_   56
#define W_   56
#define HW_  3136
#define CO_  256
#define HP_  58
#define WP_  58

// ---------------- scratch (__device__ globals: allocation-free rule) -------
__device__ int8_t g_xpad[(size_t)B_ * HP_ * WP_ * CI_];   // NHWC padded signs
__device__ int8_t g_wsign[9 * CO_ * CI_];                 // [tap][co][ci]
__device__ float  g_coeff[CO_];

// ---------------- helpers ---------------------------------------------------
__device__ __forceinline__ uint32_t s2u(const void* p) {
    uint32_t a;
    asm("{ .reg .u64 t; cvta.to.shared.u64 t, %1; cvt.u32.u64 %0, t; }"
        : "=r"(a) : "l"(p));
    return a;
}
__device__ __forceinline__ void cpa16(uint32_t d, const void* g) {
    asm volatile("cp.async.cg.shared.global [%0], [%1], 16;" :: "r"(d), "l"(g) : "memory");
}
__device__ __forceinline__ void imma(int* c, const uint32_t* a, uint32_t b0, uint32_t b1) {
    asm volatile(
        "mma.sync.aligned.m16n8k32.row.col.s32.s8.s8.s32 "
        "{%0,%1,%2,%3}, {%4,%5,%6,%7}, {%8,%9}, {%0,%1,%2,%3};"
        : "+r"(c[0]), "+r"(c[1]), "+r"(c[2]), "+r"(c[3])
        : "r"(a[0]), "r"(a[1]), "r"(a[2]), "r"(a[3]), "r"(b0), "r"(b1));
}
__device__ __forceinline__ void ldm4(uint32_t* r, uint32_t addr) {
    asm volatile("ldmatrix.sync.aligned.m8n8.x4.shared.b16 {%0,%1,%2,%3}, [%4];"
                 : "=r"(r[0]), "=r"(r[1]), "=r"(r[2]), "=r"(r[3]) : "r"(addr));
}

// ---------------- kernel A: weights -> int8 signs + coeff -------------------
__global__ void prep_weights(const float* __restrict__ w,
                             const float* __restrict__ rv,
                             const float* __restrict__ alpha) {
    int co = blockIdx.x, ci = threadIdx.x;
    float r0 = rv[0], r1 = rv[1], r2 = rv[2], r3 = rv[3];
    const size_t ks = (size_t)CO_ * CI_ * 9;
    const float* p = w + ((size_t)co * CI_ + ci) * 9;
    float asum = 0.f;
#pragma unroll
    for (int t = 0; t < 9; t++) {
        float v = r0 * p[t] + r1 * p[ks + t] + r2 * p[2 * ks + t] + r3 * p[3 * ks + t];
        asum += fabsf(v);
        g_wsign[((size_t)t * CO_ + co) * CI_ + ci] = v > 0.f ? 1 : (v < 0.f ? -1 : 0);
    }
    __shared__ float red[256];
    red[ci] = asum;
    __syncthreads();
    for (int s = 128; s > 0; s >>= 1) {
        if (ci < s) red[ci] += red[ci + s];
        __syncthreads();
    }
    if (ci == 0) g_coeff[co] = alpha[co] * (red[0] / 2304.0f);
}

// ---------------- kernel B0: zero the pad ring ------------------------------
__global__ void zero_pad() {
    int b = blockIdx.y, i = blockIdx.x, t = threadIdx.x;
    int r, c;
    if (i < 58)       { r = 0;  c = i; }
    else if (i < 116) { r = 57; c = i - 58; }
    else { int j = i - 116; r = 1 + (j >> 1); c = (j & 1) * 57; }
    uint2* dst = (uint2*)&g_xpad[(((size_t)b * HP_ + r) * WP_ + c) * CI_];
    dst[t] = make_uint2(0, 0);
}

// ---------------- kernel B1: NCHW f32 -> NHWC-padded int8 signs -------------
__global__ void pack_x(const float* __restrict__ x) {
    __shared__ uint32_t tile[32][65];
    int b = blockIdx.y;
    int hw0 = blockIdx.x * 32;
    int tid = threadIdx.x;
    int tx = tid & 31, ty = tid >> 5;
    const float* xp = x + (size_t)b * CI_ * HW_ + hw0 + tx;
#pragma unroll
    for (int k4 = 0; k4 < 8; k4++) {
        uint32_t pk = 0;
#pragma unroll
        for (int j = 0; j < 4; j++) {
            int ci = ty * 32 + k4 * 4 + j;
            float v = xp[(size_t)ci * HW_];
            int8_t s = v > 0.f ? 1 : (v < 0.f ? -1 : 0);
            pk |= ((uint32_t)(uint8_t)s) << (8 * j);
        }
        tile[tx][ty * 8 + k4] = pk;
    }
    __syncthreads();
    int p = tid >> 3, c8 = tid & 7;
    int hw = hw0 + p;
    int r = hw / 56, c = hw - r * 56;
    uint4* d = (uint4*)&g_xpad[(((size_t)b * HP_ + r + 1) * WP_ + c + 1) * CI_ + c8 * 32];
    d[0] = make_uint4(tile[p][c8 * 8 + 0], tile[p][c8 * 8 + 1],
                      tile[p][c8 * 8 + 2], tile[p][c8 * 8 + 3]);
    d[1] = make_uint4(tile[p][c8 * 8 + 4], tile[p][c8 * 8 + 5],
                      tile[p][c8 * 8 + 6], tile[p][c8 * 8 + 7]);
}

// ---------------- kernel C: A-resident int8 IMMA conv, 2 CTAs/SM ------------
// CTA: 256 thr, 8 warps (2m x 4n), warp tile 64x32.
// M=128 px (2 output rows x 56 + 16 dup) x N=128 co.
// A: 4 input rows x 58 x 256 = 58KB resident. B: 18 chunks, 3-stage (16KB).
#define A_SZ   59392              // 4*58*256
#define STG    16384
#define NSTG   3
#define CF_OFF (A_SZ + NSTG * STG)
#define SMEM_DYN (CF_OFF + 512)   // 109056 B -> 2 CTAs/SM

__device__ __forceinline__ void load_B(uint32_t sbA, int slot, int i, int coBase,
                                       int tid) {
    int tap = i >> 1, ciofs = (i & 1) << 7;
    uint32_t stg = sbA + A_SZ + slot * STG;
#pragma unroll
    for (int t = 0; t < 4; t++) {
        int idx = tid + t * 256;
        int r = idx >> 3, e = idx & 7;
        const void* g = &g_wsign[((size_t)tap * CO_ + coBase + r) * CI_ + ciofs + e * 16];
        cpa16(stg + r * 128 + ((e ^ (r & 7)) << 4), g);
    }
}

__global__ void __launch_bounds__(256, 2) bconv_imma(float* __restrict__ out) {
    extern __shared__ char smem[];
    uint32_t sbA = s2u(smem);
    int tid = threadIdx.x, wid = tid >> 5, lane = tid & 31;
    int g = lane >> 2, tg = lane & 3;
    int wm = wid >> 2, wn = wid & 3;          // 2 x 4 warp grid
    int r0 = blockIdx.x * 2, coBase = blockIdx.y * 128, b = blockIdx.z;

    float* cf = (float*)(smem + CF_OFF);
    if (tid < 128) cf[tid] = g_coeff[coBase + tid];

    // ---- prologue: A resident (4 rows, contiguous 58KB) + B0, B1 ----
    {
        const int8_t* gA = &g_xpad[(((size_t)b * HP_ + r0) * WP_) * CI_];
        for (int idx = tid; idx < A_SZ / 16; idx += 256) {
            int lin = idx >> 4, ch = idx & 15;
            cpa16(sbA + lin * 256 + ((ch ^ (lin & 7)) << 4), gA + (size_t)idx * 16);
        }
        asm volatile("cp.async.commit_group;" ::: "memory");
        load_B(sbA, 0, 0, coBase, tid);
        asm volatile("cp.async.commit_group;" ::: "memory");
        load_B(sbA, 1, 1, coBase, tid);
        asm volatile("cp.async.commit_group;" ::: "memory");
    }

    // per-lane fragment geometry
    int t8 = lane >> 3, lr = lane & 7;
    int khalf = t8 >> 1, rsel = (t8 & 1) * 8;
    int lin0[4];
#pragma unroll
    for (int mf = 0; mf < 4; mf++) {
        int m = wm * 64 + mf * 16 + rsel + lr;
        if (m < 112) { int j = m >= 56; lin0[mf] = j * 58 + (m - (j ? 56 : 0)); }
        else lin0[mf] = 0;
    }
    int rowB0 = wn * 32 + rsel + lr;
    int rowB1 = rowB0 + 16;
    uint32_t bB0 = rowB0 * 128 + A_SZ, bB1 = rowB1 * 128 + A_SZ;
    int xB0 = rowB0 & 7, xB1 = rowB1 & 7;

    int acc[4][4][4];
#pragma unroll
    for (int mf = 0; mf < 4; mf++)
#pragma unroll
        for (int nf = 0; nf < 4; nf++)
#pragma unroll
            for (int e = 0; e < 4; e++) acc[mf][nf][e] = 0;

    asm volatile("cp.async.wait_group 1;" ::: "memory");   // A + B0 landed
    __syncthreads();

    for (int i = 0; i < 18; i++) {
        // prefetch chunk i+2 into slot (i+2)%3 (freed by barrier at end of i-1)
        if (i + 2 < 18) load_B(sbA, (i + 2) % 3, i + 2, coBase, tid);
        asm volatile("cp.async.commit_group;" ::: "memory");

        int tap = i >> 1, cihalf = i & 1;
        int kh = tap / 3, kw = tap - kh * 3;
        int dlin = kh * 58 + kw;
        uint32_t aBase[4]; int x7[4];
#pragma unroll
        for (int mf = 0; mf < 4; mf++) {
            int lin = lin0[mf] + dlin;
            aBase[mf] = sbA + lin * 256;
            x7[mf] = lin & 7;
        }
        uint32_t bS = sbA + (i % 3) * STG;

#pragma unroll
        for (int s = 0; s < 4; s++) {
            int c16a = cihalf * 8 + s * 2 + khalf;
            int c16b = s * 2 + khalf;
            uint32_t a[4][4], bb[2][4];
#pragma unroll
            for (int mf = 0; mf < 4; mf++)
                ldm4(a[mf], aBase[mf] + ((c16a ^ x7[mf]) << 4));
            ldm4(bb[0], bS + bB0 + ((c16b ^ xB0) << 4));
            ldm4(bb[1], bS + bB1 + ((c16b ^ xB1) << 4));
#pragma unroll
            for (int mf = 0; mf < 4; mf++)
#pragma unroll
                for (int p = 0; p < 2; p++) {
                    imma(acc[mf][2 * p],     a[mf], bb[p][0], bb[p][2]);
                    imma(acc[mf][2 * p + 1], a[mf], bb[p][1], bb[p][3]);
                }
        }

        // ensure chunk i+1 landed (<=1 group pending) before next compute
        asm volatile("cp.async.wait_group 1;" ::: "memory");
        __syncthreads();
    }

    // ---- epilogue: out[b][co][h][w] = coeff[co] * acc (NCHW) ----
    float* obase = out + (size_t)b * CO_ * HW_;
#pragma unroll
    for (int mf = 0; mf < 4; mf++) {
#pragma unroll
        for (int half = 0; half < 2; half++) {
            int px = wm * 64 + mf * 16 + g + 8 * half;
            if (px < 112) {
                int j = px >= 56;
                int h = r0 + j;
                int w = px - (j ? 56 : 0);
#pragma unroll
                for (int nf = 0; nf < 4; nf++) {
                    int cl = wn * 32 + nf * 8 + tg * 2;
                    float* o = obase + (size_t)(coBase + cl) * HW_ + h * 56 + w;
                    o[0]   = cf[cl]     * (float)acc[mf][nf][half * 2];
                    o[HW_] = cf[cl + 1] * (float)acc[mf][nf][half * 2 + 1];
                }
            }
        }
    }
}

// ---------------------------------------------------------------------------
extern "C" void kernel_launch(void* const* d_in, const int* in_sizes, int n_in,
                              void* d_out, int out_size) {
    const float *x = nullptr, *wt = nullptr, *rv = nullptr, *al = nullptr;
    for (int i = 0; i < n_in; i++) {
        switch (in_sizes[i]) {
            case 25690112: x  = (const float*)d_in[i]; break;
            case 2359296:  wt = (const float*)d_in[i]; break;
            case 5:        rv = (const float*)d_in[i]; break;
            case 256:      al = (const float*)d_in[i]; break;
        }
    }

    prep_weights<<<256, 256>>>(wt, rv, al);

    dim3 gz(228, 32);
    zero_pad<<<gz, 32>>>();

    dim3 gp(98, 32);
    pack_x<<<gp, 256>>>(x);

    static int smem_set = 0;
    if (!smem_set) {
        cudaFuncSetAttribute(bconv_imma, cudaFuncAttributeMaxDynamicSharedMemorySize,
                             SMEM_DYN);
        smem_set = 1;
    }
    dim3 gc(28, 2, 32);
    bconv_imma<<<gc, 256, SMEM_DYN>>>((float*)d_out);
}